// round 5
// baseline (speedup 1.0000x reference)
#include <cuda_runtime.h>

#define N_NODES  100000
#define N_EDGES  3200000
#define N_GRAPHS 256

static __device__ int   g_is64;
static __device__ int2  g_ecsr[N_EDGES];      // per CSR slot: {src, __float_as_int(norm)}
static __device__ int   g_cnt[N_NODES];
static __device__ int   g_rowptr[N_NODES + 1];
static __device__ int   g_cursor[N_NODES];
static __device__ float g_dinv[N_NODES];
static __device__ float g_selfw[N_NODES];
static __device__ __align__(16) float g_bufA[(size_t)N_NODES * 128];
static __device__ __align__(16) float g_bufB[(size_t)N_NODES * 128];
static __device__ float g_psum[N_GRAPHS * 64];
static __device__ int   g_pcnt[N_GRAPHS];
static __device__ int   g_bsum[128];
static __device__ int   g_boff[128];

static constexpr int SCAN_CHUNK  = 1024;
static constexpr int SCAN_BLOCKS = (N_NODES + SCAN_CHUNK - 1) / SCAN_CHUNK;

// ------------------------------------------------------------- f32x2 helpers

typedef unsigned long long ull;

__device__ __forceinline__ ull pack2(float x, float y) {
    ull r; asm("mov.b64 %0, {%1,%2};" : "=l"(r) : "f"(x), "f"(y)); return r;
}
__device__ __forceinline__ float2 unpack2(ull v) {
    float x, y; asm("mov.b64 {%0,%1}, %2;" : "=f"(x), "=f"(y) : "l"(v));
    return make_float2(x, y);
}
__device__ __forceinline__ ull fma2(ull a, ull b, ull c) {
    ull d; asm("fma.rn.f32x2 %0, %1, %2, %3;" : "=l"(d) : "l"(a), "l"(b), "l"(c));
    return d;
}

// ---------------------------------------------------------------- utilities

__global__ void zero_detect_kernel(const int* __restrict__ ei32) {
    int i = blockIdx.x * blockDim.x + threadIdx.x;
    if (i < N_NODES)      g_cnt[i]  = 0;
    if (i < N_GRAPHS*64)  g_psum[i] = 0.f;
    if (i < N_GRAPHS)     g_pcnt[i] = 0;
    if (i == 0) {
        // int64 tensors have the high int32 word zero for values < 2^31
        int allz = 1;
        for (int k = 1; k < 256; k += 2) allz &= (ei32[k] == 0);
        g_is64 = allz;
    }
}

// Histogram of dst degrees; reads only the dst row of edge_index.
__global__ void hist_kernel(const void* __restrict__ eidx) {
    int e = blockIdx.x * blockDim.x + threadIdx.x;
    if (e >= N_EDGES) return;
    int d;
    if (g_is64) d = (int)((const long long*)eidx)[(size_t)N_EDGES + e];
    else        d = ((const int*)eidx)[N_EDGES + e];
    atomicAdd(&g_cnt[d], 1);
}

// ---------------------------------------------------------------- prefix scan

__global__ void scan1_kernel() {
    __shared__ int s[SCAN_CHUNK];
    int tid = threadIdx.x;
    int i = blockIdx.x * SCAN_CHUNK + tid;
    int v = (i < N_NODES) ? g_cnt[i] : 0;
    s[tid] = v;
    __syncthreads();
    for (int off = 1; off < SCAN_CHUNK; off <<= 1) {
        int t = (tid >= off) ? s[tid - off] : 0;
        __syncthreads();
        s[tid] += t;
        __syncthreads();
    }
    if (i < N_NODES) g_rowptr[i] = s[tid] - v;   // exclusive, pre-offset
    if (tid == SCAN_CHUNK - 1) g_bsum[blockIdx.x] = s[tid];
}

__global__ void scan2_kernel() {
    if (threadIdx.x == 0) {
        int run = 0;
        for (int b = 0; b < SCAN_BLOCKS; b++) { g_boff[b] = run; run += g_bsum[b]; }
    }
}

__global__ void scan3_kernel() {
    int i = blockIdx.x * blockDim.x + threadIdx.x;
    if (i > N_NODES) return;
    if (i == N_NODES) { g_rowptr[N_NODES] = N_EDGES; return; }
    int rp = g_rowptr[i] + g_boff[i / SCAN_CHUNK];
    g_rowptr[i] = rp;
    g_cursor[i] = rp;
    float deg = (float)g_cnt[i] + 1.0f;
    g_dinv[i]  = rsqrtf(deg);
    g_selfw[i] = 1.0f / deg;
}

// Cursor-scatter into CSR; precompute per-edge symmetric norm here so the
// aggregation loops never gather dinv.
__global__ void fill_kernel(const void* __restrict__ eidx) {
    int e = blockIdx.x * blockDim.x + threadIdx.x;
    if (e >= N_EDGES) return;
    int s, d;
    if (g_is64) {
        const long long* p = (const long long*)eidx;
        s = (int)p[e];
        d = (int)p[(size_t)N_EDGES + e];
    } else {
        const int* p = (const int*)eidx;
        s = p[e];
        d = p[N_EDGES + e];
    }
    float norm = g_dinv[s] * g_dinv[d];
    int slot = atomicAdd(&g_cursor[d], 1);
    g_ecsr[slot] = make_int2(s, __float_as_int(norm));
}

// ---------------------------------------------------------------- aggregation

// F=8 aggregation of raw x into bufA. One warp per node, edge-parallel lanes.
__global__ void aggX_kernel(const float* __restrict__ x) {
    int w = (blockIdx.x * blockDim.x + threadIdx.x) >> 5;
    if (w >= N_NODES) return;
    int lane = threadIdx.x & 31;
    int beg = g_rowptr[w], end = g_rowptr[w + 1];
    ull a01 = 0, a23 = 0, a45 = 0, a67 = 0;
    for (int e = beg + lane; e < end; e += 32) {
        int2 t = g_ecsr[e];
        int s = t.x;
        float nrm = __int_as_float(t.y);
        ull np = pack2(nrm, nrm);
        const ull* xp = (const ull*)(x + (size_t)s * 8);
        a01 = fma2(np, xp[0], a01);
        a23 = fma2(np, xp[1], a23);
        a45 = fma2(np, xp[2], a45);
        a67 = fma2(np, xp[3], a67);
    }
    float2 p0 = unpack2(a01), p1 = unpack2(a23), p2 = unpack2(a45), p3 = unpack2(a67);
    float a0=p0.x,a1=p0.y,a2=p1.x,a3=p1.y,a4=p2.x,a5=p2.y,a6=p3.x,a7=p3.y;
    #pragma unroll
    for (int off = 16; off; off >>= 1) {
        a0 += __shfl_xor_sync(0xffffffffu, a0, off);
        a1 += __shfl_xor_sync(0xffffffffu, a1, off);
        a2 += __shfl_xor_sync(0xffffffffu, a2, off);
        a3 += __shfl_xor_sync(0xffffffffu, a3, off);
        a4 += __shfl_xor_sync(0xffffffffu, a4, off);
        a5 += __shfl_xor_sync(0xffffffffu, a5, off);
        a6 += __shfl_xor_sync(0xffffffffu, a6, off);
        a7 += __shfl_xor_sync(0xffffffffu, a7, off);
    }
    if (lane == 0) {
        float sw = g_selfw[w];
        const float4* xp = (const float4*)(x + (size_t)w * 8);
        float4 u = xp[0], v = xp[1];
        float4 o0 = make_float4(a0 + sw*u.x, a1 + sw*u.y, a2 + sw*u.z, a3 + sw*u.w);
        float4 o1 = make_float4(a4 + sw*v.x, a5 + sw*v.y, a6 + sw*v.z, a7 + sw*v.w);
        float4* op = (float4*)(g_bufA + (size_t)w * 8);
        op[0] = o0; op[1] = o1;
    }
}

// F=64 aggregation. One warp per dst node, lane owns a float2 column pair.
// 4-way edge unroll for memory-level parallelism; packed f32x2 accumulation.
template <bool BIAS_RELU>
__global__ void agg64_kernel(int inB, int outB, const float* __restrict__ bias) {
    int w = (blockIdx.x * blockDim.x + threadIdx.x) >> 5;
    if (w >= N_NODES) return;
    int lane = threadIdx.x & 31;
    int c = lane * 2;
    const float* __restrict__ in  = inB  ? g_bufB : g_bufA;
    float*       __restrict__ out = outB ? g_bufB : g_bufA;
    int e = g_rowptr[w], end = g_rowptr[w + 1];
    ull acc0 = 0, acc1 = 0, acc2 = 0, acc3 = 0;
    for (; e + 4 <= end; e += 4) {
        int2 t0 = g_ecsr[e+0], t1 = g_ecsr[e+1], t2 = g_ecsr[e+2], t3 = g_ecsr[e+3];
        float n0 = __int_as_float(t0.y), n1 = __int_as_float(t1.y);
        float n2 = __int_as_float(t2.y), n3 = __int_as_float(t3.y);
        ull v0 = *(const ull*)(in + (size_t)t0.x*64 + c);
        ull v1 = *(const ull*)(in + (size_t)t1.x*64 + c);
        ull v2 = *(const ull*)(in + (size_t)t2.x*64 + c);
        ull v3 = *(const ull*)(in + (size_t)t3.x*64 + c);
        acc0 = fma2(pack2(n0, n0), v0, acc0);
        acc1 = fma2(pack2(n1, n1), v1, acc1);
        acc2 = fma2(pack2(n2, n2), v2, acc2);
        acc3 = fma2(pack2(n3, n3), v3, acc3);
    }
    for (; e < end; e++) {
        int2 t = g_ecsr[e];
        float nn = __int_as_float(t.y);
        ull v = *(const ull*)(in + (size_t)t.x*64 + c);
        acc0 = fma2(pack2(nn, nn), v, acc0);
    }
    float2 s0 = unpack2(acc0), s1 = unpack2(acc1), s2 = unpack2(acc2), s3 = unpack2(acc3);
    float sw = g_selfw[w];
    float2 sv = *(const float2*)(in + (size_t)w*64 + c);
    float ox = (s0.x + s1.x) + (s2.x + s3.x) + sw * sv.x;
    float oy = (s0.y + s1.y) + (s2.y + s3.y) + sw * sv.y;
    if (BIAS_RELU) {
        ox = fmaxf(ox + bias[c],     0.f);
        oy = fmaxf(oy + bias[c + 1], 0.f);
    }
    *(float2*)(out + (size_t)w*64 + c) = make_float2(ox, oy);
}

// ---------------------------------------------------------------- GEMM

// Node-parallel GEMM, grid-stride over node tiles so W is staged in smem once
// per block. Each thread computes CPT contiguous output columns for one node,
// with packed f32x2 FMAs.
template <int IN, int OUT, int CPT, bool ACT>
__global__ void gemm_kernel(int inB, const float* __restrict__ W,
                            const float* __restrict__ bias, int outB) {
    constexpr int TPN = OUT / CPT;      // threads per node
    constexpr int NPB = 256 / TPN;      // nodes per block-tile
    __shared__ __align__(16) float sW[IN * OUT];
    __shared__ float sB[OUT];
    __shared__ float sH[NPB * IN];
    const float* __restrict__ in  = inB  ? g_bufB : g_bufA;
    float*       __restrict__ out = outB ? g_bufB : g_bufA;
    int tid = threadIdx.x;
    for (int i = tid; i < IN * OUT; i += 256) sW[i] = W[i];
    if (tid < OUT) sB[tid] = bias ? bias[tid] : 0.f;
    int nd = tid / TPN, cg = tid % TPN;

    for (int base = blockIdx.x * NPB; base < N_NODES; base += gridDim.x * NPB) {
        __syncthreads();   // previous tile's compute done / sW ready on first pass
        for (int i = tid; i < NPB * IN; i += 256) {
            int node = base + i / IN;
            sH[i] = (node < N_NODES) ? in[(size_t)node * IN + (i % IN)] : 0.f;
        }
        __syncthreads();
        int node = base + nd;
        if (node < N_NODES) {
            ull acc[CPT / 2];
            #pragma unroll
            for (int q = 0; q < CPT / 2; q++)
                acc[q] = pack2(sB[cg * CPT + 2*q], sB[cg * CPT + 2*q + 1]);
            const float* hrow = &sH[nd * IN];
            #pragma unroll 4
            for (int k = 0; k < IN; k++) {
                float a = hrow[k];
                ull ap = pack2(a, a);
                const ull* wp = reinterpret_cast<const ull*>(sW + k * OUT + cg * CPT);
                #pragma unroll
                for (int q = 0; q < CPT / 2; q++)
                    acc[q] = fma2(ap, wp[q], acc[q]);
            }
            float* op = out + (size_t)node * OUT + cg * CPT;
            #pragma unroll
            for (int q = 0; q < CPT / 2; q++) {
                float2 v = unpack2(acc[q]);
                if (ACT) { v.x = fmaxf(v.x, 0.f); v.y = fmaxf(v.y, 0.f); }
                *(float2*)(op + 2*q) = v;
            }
        }
    }
}

// ---------------------------------------------------------------- pooling + MLP

// batch is sorted: warp sweeps 64 consecutive nodes, accumulating in registers,
// flushing with atomics only on graph-id changes.
__global__ void pool_kernel(const void* __restrict__ batch) {
    int w = (blockIdx.x * blockDim.x + threadIdx.x) >> 5;
    int lane = threadIdx.x & 31;
    const int NPW = 64;
    int start = w * NPW;
    if (start >= N_NODES) return;
    int end = min(start + NPW, N_NODES);
    int is64 = g_is64;
    int c = lane * 2;
    float ax = 0.f, ay = 0.f;
    int curg = -1, cnt = 0;
    for (int i = start; i < end; i++) {
        int g = is64 ? (int)((const long long*)batch)[i] : ((const int*)batch)[i];
        if (g != curg) {
            if (curg >= 0) {
                atomicAdd(&g_psum[curg * 64 + c],     ax);
                atomicAdd(&g_psum[curg * 64 + c + 1], ay);
                if (lane == 0) atomicAdd(&g_pcnt[curg], cnt);
            }
            curg = g; ax = 0.f; ay = 0.f; cnt = 0;
        }
        float2 v = *(const float2*)(g_bufB + (size_t)i * 64 + c);
        ax += v.x; ay += v.y; cnt++;
    }
    if (curg >= 0) {
        atomicAdd(&g_psum[curg * 64 + c],     ax);
        atomicAdd(&g_psum[curg * 64 + c + 1], ay);
        if (lane == 0) atomicAdd(&g_pcnt[curg], cnt);
    }
}

__global__ void mlp_kernel(const float* __restrict__ Wl1, const float* __restrict__ bl1,
                           const float* __restrict__ Wl2, const float* __restrict__ bl2,
                           float* __restrict__ out) {
    __shared__ float sW1[64 * 32];
    __shared__ float sb1[32];
    __shared__ float sW2[32];
    __shared__ float sb2;
    int tid = threadIdx.x;
    for (int i = tid; i < 64 * 32; i += 256) sW1[i] = Wl1[i];
    if (tid < 32) { sb1[tid] = bl1[tid]; sW2[tid] = Wl2[tid]; }
    if (tid == 0) sb2 = bl2[0];
    __syncthreads();
    float inv = 1.0f / fmaxf((float)g_pcnt[tid], 1.0f);
    float hid[32];
    #pragma unroll
    for (int cc = 0; cc < 32; cc++) hid[cc] = sb1[cc];
    for (int k = 0; k < 64; k++) {
        float a = g_psum[tid * 64 + k] * inv;
        #pragma unroll
        for (int cc = 0; cc < 32; cc++) hid[cc] = fmaf(a, sW1[k * 32 + cc], hid[cc]);
    }
    float o = sb2;
    #pragma unroll
    for (int cc = 0; cc < 32; cc++) o = fmaf(fmaxf(hid[cc], 0.f), sW2[cc], o);
    out[tid] = o;
}

// ---------------------------------------------------------------- launch

extern "C" void kernel_launch(void* const* d_in, const int* in_sizes, int n_in,
                              void* d_out, int out_size) {
    const float* x    = (const float*)d_in[0];
    const void*  eidx = d_in[1];
    const void*  batch= d_in[2];
    const float* W1   = (const float*)d_in[3];
    const float* b1   = (const float*)d_in[4];
    const float* W2   = (const float*)d_in[5];
    const float* b2   = (const float*)d_in[6];
    const float* W3   = (const float*)d_in[7];
    const float* b3   = (const float*)d_in[8];
    const float* Wl1  = (const float*)d_in[9];
    const float* bl1  = (const float*)d_in[10];
    const float* Wl2  = (const float*)d_in[11];
    const float* bl2  = (const float*)d_in[12];
    float* out = (float*)d_out;

    const int warpGrid = (N_NODES * 32 + 255) / 256;
    const int GEMM_GRID = 1184;   // 8 blocks/SM × 148 SMs

    zero_detect_kernel<<<(N_NODES + 255) / 256, 256>>>((const int*)eidx);
    hist_kernel  <<<(N_EDGES + 255) / 256, 256>>>(eidx);
    scan1_kernel <<<SCAN_BLOCKS, SCAN_CHUNK>>>();
    scan2_kernel <<<1, 32>>>();
    scan3_kernel <<<(N_NODES + 1 + 255) / 256, 256>>>();
    fill_kernel  <<<(N_EDGES + 255) / 256, 256>>>(eidx);

    // Layer 1: aggregate x (8-d), then GEMM 8->64 (+b1, relu)
    aggX_kernel<<<warpGrid, 256>>>(x);
    gemm_kernel<8, 64, 8, true><<<GEMM_GRID, 256>>>(0, W1, b1, 1);
    // Layer 2: aggregate h1 (64-d), then GEMM 64->128 (+b2, relu)
    agg64_kernel<false><<<warpGrid, 256>>>(1, 0, nullptr);
    gemm_kernel<64, 128, 8, true><<<GEMM_GRID, 256>>>(0, W2, b2, 1);
    // Layer 3: GEMM 128->64 first, then aggregate (+b3, relu)
    gemm_kernel<128, 64, 4, false><<<GEMM_GRID, 256>>>(1, W3, nullptr, 0);
    agg64_kernel<true><<<warpGrid, 256>>>(0, 1, b3);

    pool_kernel<<<(((N_NODES + 63) / 64) * 32 + 255) / 256, 256>>>(batch);
    mlp_kernel<<<1, 256>>>(Wl1, bl1, Wl2, bl2, out);
}

// round 6
// speedup vs baseline: 1.5940x; 1.5940x over previous
#include <cuda_runtime.h>

#define N_NODES  100000
#define N_EDGES  3200000
#define N_GRAPHS 256

static __device__ int   g_is64;
static __device__ int   g_src[N_EDGES];
static __device__ int   g_dst[N_EDGES];
static __device__ int   g_ssrc[N_EDGES];      // src sorted by dst (CSR payload)
static __device__ int   g_cnt[N_NODES];
static __device__ int   g_rowptr[N_NODES + 1];
static __device__ int   g_cursor[N_NODES];
static __device__ float g_dinv[N_NODES];
static __device__ __align__(16) float g_xs[(size_t)N_NODES * 8];   // x * dinv
static __device__ __align__(16) float g_bufA[(size_t)N_NODES * 128];
static __device__ __align__(16) float g_bufB[(size_t)N_NODES * 128];
static __device__ float g_psum[N_GRAPHS * 64];
static __device__ int   g_pcnt[N_GRAPHS];
static __device__ int   g_bsum[128];
static __device__ int   g_boff[128];

static constexpr int SCAN_CHUNK  = 1024;
static constexpr int SCAN_BLOCKS = (N_NODES + SCAN_CHUNK - 1) / SCAN_CHUNK;

// ---------------------------------------------------------------- utilities

__global__ void zero_kernel() {
    int i = blockIdx.x * blockDim.x + threadIdx.x;
    if (i < N_NODES)      g_cnt[i]  = 0;
    if (i < N_GRAPHS*64)  g_psum[i] = 0.f;
    if (i < N_GRAPHS)     g_pcnt[i] = 0;
}

// Detect whether edge_index arrived as int64 (odd int32 words all zero) or int32.
__global__ void detect_kernel(const int* __restrict__ ei32) {
    if (threadIdx.x == 0 && blockIdx.x == 0) {
        int allz = 1;
        for (int i = 1; i < 256; i += 2) allz &= (ei32[i] == 0);
        g_is64 = allz;
    }
}

__global__ void convert_kernel(const void* __restrict__ eidx) {
    int e = blockIdx.x * blockDim.x + threadIdx.x;
    if (e >= N_EDGES) return;
    int s, d;
    if (g_is64) {
        const long long* p = (const long long*)eidx;
        s = (int)p[e];
        d = (int)p[(size_t)N_EDGES + e];
    } else {
        const int* p = (const int*)eidx;
        s = p[e];
        d = p[N_EDGES + e];
    }
    g_src[e] = s;
    g_dst[e] = d;
    atomicAdd(&g_cnt[d], 1);
}

// ---------------------------------------------------------------- prefix scan

__global__ void scan1_kernel() {
    __shared__ int s[SCAN_CHUNK];
    int tid = threadIdx.x;
    int i = blockIdx.x * SCAN_CHUNK + tid;
    int v = (i < N_NODES) ? g_cnt[i] : 0;
    s[tid] = v;
    __syncthreads();
    for (int off = 1; off < SCAN_CHUNK; off <<= 1) {
        int t = (tid >= off) ? s[tid - off] : 0;
        __syncthreads();
        s[tid] += t;
        __syncthreads();
    }
    if (i < N_NODES) g_rowptr[i] = s[tid] - v;   // exclusive, pre-offset
    if (tid == SCAN_CHUNK - 1) g_bsum[blockIdx.x] = s[tid];
}

// Parallel block-level exclusive scan over the 98 block sums (was serial, 11.5us).
__global__ void scan2_kernel() {
    __shared__ int s[128];
    int t = threadIdx.x;
    int v = (t < SCAN_BLOCKS) ? g_bsum[t] : 0;
    s[t] = v;
    __syncthreads();
    for (int off = 1; off < 128; off <<= 1) {
        int u = (t >= off) ? s[t - off] : 0;
        __syncthreads();
        s[t] += u;
        __syncthreads();
    }
    if (t < SCAN_BLOCKS) g_boff[t] = s[t] - v;
}

// Finalize rowptr/cursor; compute dinv; pre-scale x by dinv (xs = x * dinv)
// so aggregation needs no per-edge normalization at all.
__global__ void scan3_kernel(const float* __restrict__ x) {
    int i = blockIdx.x * blockDim.x + threadIdx.x;
    if (i > N_NODES) return;
    if (i == N_NODES) { g_rowptr[N_NODES] = N_EDGES; return; }
    int rp = g_rowptr[i] + g_boff[i / SCAN_CHUNK];
    g_rowptr[i] = rp;
    g_cursor[i] = rp;
    float deg = (float)g_cnt[i] + 1.0f;
    float dv = rsqrtf(deg);
    g_dinv[i] = dv;
    const float4* xp = (const float4*)(x + (size_t)i * 8);
    float4 u = xp[0], v4 = xp[1];
    float4* op = (float4*)(g_xs + (size_t)i * 8);
    op[0] = make_float4(u.x * dv, u.y * dv, u.z * dv, u.w * dv);
    op[1] = make_float4(v4.x * dv, v4.y * dv, v4.z * dv, v4.w * dv);
}

__global__ void fill_kernel() {
    int e = blockIdx.x * blockDim.x + threadIdx.x;
    if (e >= N_EDGES) return;
    int d = g_dst[e];
    int slot = atomicAdd(&g_cursor[d], 1);
    g_ssrc[slot] = g_src[e];
}

// ---------------------------------------------------------------- aggregation
//
// With h' = dinv*h pre-scaled by the producer, GCN aggregation is exactly:
//   out_i = dinv_i * (h'_i + sum_{j in N(i)} h'_j)
// so the per-edge work is a pure gather+add (no norm load, no multiply).

// F=8 aggregation of xs into bufA. One warp per node, edge-parallel lanes.
__global__ void aggX_kernel() {
    int w = (blockIdx.x * blockDim.x + threadIdx.x) >> 5;
    if (w >= N_NODES) return;
    int lane = threadIdx.x & 31;
    int beg = g_rowptr[w], end = g_rowptr[w + 1];
    float a0=0,a1=0,a2=0,a3=0,a4=0,a5=0,a6=0,a7=0;
    for (int e = beg + lane; e < end; e += 32) {
        int s = g_ssrc[e];
        const float4* xp = (const float4*)(g_xs + (size_t)s * 8);
        float4 u = xp[0], v = xp[1];
        a0 += u.x; a1 += u.y; a2 += u.z; a3 += u.w;
        a4 += v.x; a5 += v.y; a6 += v.z; a7 += v.w;
    }
    #pragma unroll
    for (int off = 16; off; off >>= 1) {
        a0 += __shfl_xor_sync(0xffffffffu, a0, off);
        a1 += __shfl_xor_sync(0xffffffffu, a1, off);
        a2 += __shfl_xor_sync(0xffffffffu, a2, off);
        a3 += __shfl_xor_sync(0xffffffffu, a3, off);
        a4 += __shfl_xor_sync(0xffffffffu, a4, off);
        a5 += __shfl_xor_sync(0xffffffffu, a5, off);
        a6 += __shfl_xor_sync(0xffffffffu, a6, off);
        a7 += __shfl_xor_sync(0xffffffffu, a7, off);
    }
    if (lane == 0) {
        float dv = g_dinv[w];
        const float4* xp = (const float4*)(g_xs + (size_t)w * 8);
        float4 u = xp[0], v = xp[1];
        float4 o0 = make_float4(dv*(a0+u.x), dv*(a1+u.y), dv*(a2+u.z), dv*(a3+u.w));
        float4 o1 = make_float4(dv*(a4+v.x), dv*(a5+v.y), dv*(a6+v.z), dv*(a7+v.w));
        float4* op = (float4*)(g_bufA + (size_t)w * 8);
        op[0] = o0; op[1] = o1;
    }
}

// F=64 aggregation. One warp per dst node, lane owns a float2 column pair.
// 4-way edge unroll for memory-level parallelism. Pure add inner loop.
template <bool BIAS_RELU>
__global__ void agg64_kernel(int inB, int outB, const float* __restrict__ bias) {
    int w = (blockIdx.x * blockDim.x + threadIdx.x) >> 5;
    if (w >= N_NODES) return;
    int lane = threadIdx.x & 31;
    int c = lane * 2;
    const float* __restrict__ in  = inB  ? g_bufB : g_bufA;
    float*       __restrict__ out = outB ? g_bufB : g_bufA;
    int e = g_rowptr[w], end = g_rowptr[w + 1];
    float ax0=0, ay0=0, ax1=0, ay1=0, ax2=0, ay2=0, ax3=0, ay3=0;
    for (; e + 4 <= end; e += 4) {
        int s0 = g_ssrc[e+0], s1 = g_ssrc[e+1], s2 = g_ssrc[e+2], s3 = g_ssrc[e+3];
        float2 v0 = *(const float2*)(in + (size_t)s0*64 + c);
        float2 v1 = *(const float2*)(in + (size_t)s1*64 + c);
        float2 v2 = *(const float2*)(in + (size_t)s2*64 + c);
        float2 v3 = *(const float2*)(in + (size_t)s3*64 + c);
        ax0 += v0.x; ay0 += v0.y;
        ax1 += v1.x; ay1 += v1.y;
        ax2 += v2.x; ay2 += v2.y;
        ax3 += v3.x; ay3 += v3.y;
    }
    for (; e < end; e++) {
        int s = g_ssrc[e];
        float2 v = *(const float2*)(in + (size_t)s*64 + c);
        ax0 += v.x; ay0 += v.y;
    }
    float dv = g_dinv[w];
    float2 sv = *(const float2*)(in + (size_t)w*64 + c);
    float ox = dv * ((ax0 + ax1) + (ax2 + ax3) + sv.x);
    float oy = dv * ((ay0 + ay1) + (ay2 + ay3) + sv.y);
    if (BIAS_RELU) {
        ox = fmaxf(ox + bias[c],     0.f);
        oy = fmaxf(oy + bias[c + 1], 0.f);
    }
    *(float2*)(out + (size_t)w*64 + c) = make_float2(ox, oy);
}

// ---------------------------------------------------------------- GEMM

// Node-parallel GEMM: block of 256 threads; W staged in smem; each thread
// computes CPT contiguous output columns for one node. SCALE multiplies the
// epilogue by dinv[node] (pre-scaling for a following aggregation pass).
template <int IN, int OUT, int CPT, bool ACT, bool SCALE>
__global__ void gemm_kernel(int inB, const float* __restrict__ W,
                            const float* __restrict__ bias, int outB) {
    constexpr int TPN = OUT / CPT;      // threads per node
    constexpr int NPB = 256 / TPN;      // nodes per block
    __shared__ __align__(16) float sW[IN * OUT];
    __shared__ float sB[OUT];
    __shared__ float sH[NPB * IN];
    const float* __restrict__ in  = inB  ? g_bufB : g_bufA;
    float*       __restrict__ out = outB ? g_bufB : g_bufA;
    int tid = threadIdx.x;
    for (int i = tid; i < IN * OUT; i += 256) sW[i] = W[i];
    if (tid < OUT) sB[tid] = bias ? bias[tid] : 0.f;
    int base = blockIdx.x * NPB;
    for (int i = tid; i < NPB * IN; i += 256) {
        int nd = i / IN, k = i % IN;
        int node = base + nd;
        sH[i] = (node < N_NODES) ? in[(size_t)node * IN + k] : 0.f;
    }
    __syncthreads();
    int nd = tid / TPN, cg = tid % TPN;
    int node = base + nd;
    if (node >= N_NODES) return;
    float acc[CPT];
    #pragma unroll
    for (int j = 0; j < CPT; j++) acc[j] = sB[cg * CPT + j];
    const float* hrow = &sH[nd * IN];
    #pragma unroll 4
    for (int k = 0; k < IN; k++) {
        float a = hrow[k];
        const float4* wp = reinterpret_cast<const float4*>(sW + k * OUT + cg * CPT);
        #pragma unroll
        for (int q = 0; q < CPT / 4; q++) {
            float4 wv = wp[q];
            acc[q*4+0] = fmaf(a, wv.x, acc[q*4+0]);
            acc[q*4+1] = fmaf(a, wv.y, acc[q*4+1]);
            acc[q*4+2] = fmaf(a, wv.z, acc[q*4+2]);
            acc[q*4+3] = fmaf(a, wv.w, acc[q*4+3]);
        }
    }
    float dv = SCALE ? g_dinv[node] : 1.0f;
    float* op = out + (size_t)node * OUT + cg * CPT;
    #pragma unroll
    for (int q = 0; q < CPT / 4; q++) {
        float4 o;
        o.x = ACT ? fmaxf(acc[q*4+0], 0.f) : acc[q*4+0];
        o.y = ACT ? fmaxf(acc[q*4+1], 0.f) : acc[q*4+1];
        o.z = ACT ? fmaxf(acc[q*4+2], 0.f) : acc[q*4+2];
        o.w = ACT ? fmaxf(acc[q*4+3], 0.f) : acc[q*4+3];
        if (SCALE) { o.x *= dv; o.y *= dv; o.z *= dv; o.w *= dv; }
        *(float4*)(op + q * 4) = o;
    }
}

// ---------------------------------------------------------------- pooling + MLP

// batch is sorted: warp sweeps 64 consecutive nodes, accumulating in registers
// and flushing with atomics only on graph-id changes (few flushes per warp).
__global__ void pool_kernel(const void* __restrict__ batch) {
    int w = (blockIdx.x * blockDim.x + threadIdx.x) >> 5;
    int lane = threadIdx.x & 31;
    const int NPW = 64;
    int start = w * NPW;
    if (start >= N_NODES) return;
    int end = min(start + NPW, N_NODES);
    int is64 = g_is64;
    int c = lane * 2;
    float ax = 0.f, ay = 0.f;
    int curg = -1, cnt = 0;
    for (int i = start; i < end; i++) {
        int g = is64 ? (int)((const long long*)batch)[i] : ((const int*)batch)[i];
        if (g != curg) {
            if (curg >= 0) {
                atomicAdd(&g_psum[curg * 64 + c],     ax);
                atomicAdd(&g_psum[curg * 64 + c + 1], ay);
                if (lane == 0) atomicAdd(&g_pcnt[curg], cnt);
            }
            curg = g; ax = 0.f; ay = 0.f; cnt = 0;
        }
        float2 v = *(const float2*)(g_bufB + (size_t)i * 64 + c);
        ax += v.x; ay += v.y; cnt++;
    }
    if (curg >= 0) {
        atomicAdd(&g_psum[curg * 64 + c],     ax);
        atomicAdd(&g_psum[curg * 64 + c + 1], ay);
        if (lane == 0) atomicAdd(&g_pcnt[curg], cnt);
    }
}

__global__ void mlp_kernel(const float* __restrict__ Wl1, const float* __restrict__ bl1,
                           const float* __restrict__ Wl2, const float* __restrict__ bl2,
                           float* __restrict__ out) {
    __shared__ float sW1[64 * 32];
    __shared__ float sb1[32];
    __shared__ float sW2[32];
    __shared__ float sb2;
    int tid = threadIdx.x;
    for (int i = tid; i < 64 * 32; i += 256) sW1[i] = Wl1[i];
    if (tid < 32) { sb1[tid] = bl1[tid]; sW2[tid] = Wl2[tid]; }
    if (tid == 0) sb2 = bl2[0];
    __syncthreads();
    float inv = 1.0f / fmaxf((float)g_pcnt[tid], 1.0f);
    float hid[32];
    #pragma unroll
    for (int cc = 0; cc < 32; cc++) hid[cc] = sb1[cc];
    for (int k = 0; k < 64; k++) {
        float a = g_psum[tid * 64 + k] * inv;
        #pragma unroll
        for (int cc = 0; cc < 32; cc++) hid[cc] = fmaf(a, sW1[k * 32 + cc], hid[cc]);
    }
    float o = sb2;
    #pragma unroll
    for (int cc = 0; cc < 32; cc++) o = fmaf(fmaxf(hid[cc], 0.f), sW2[cc], o);
    out[tid] = o;
}

// ---------------------------------------------------------------- launch

extern "C" void kernel_launch(void* const* d_in, const int* in_sizes, int n_in,
                              void* d_out, int out_size) {
    const float* x    = (const float*)d_in[0];
    const void*  eidx = d_in[1];
    const void*  batch= d_in[2];
    const float* W1   = (const float*)d_in[3];
    const float* b1   = (const float*)d_in[4];
    const float* W2   = (const float*)d_in[5];
    const float* b2   = (const float*)d_in[6];
    const float* W3   = (const float*)d_in[7];
    const float* b3   = (const float*)d_in[8];
    const float* Wl1  = (const float*)d_in[9];
    const float* bl1  = (const float*)d_in[10];
    const float* Wl2  = (const float*)d_in[11];
    const float* bl2  = (const float*)d_in[12];
    float* out = (float*)d_out;

    const int warpGrid = (N_NODES * 32 + 255) / 256;

    zero_kernel   <<<(N_NODES + 255) / 256, 256>>>();
    detect_kernel <<<1, 32>>>((const int*)eidx);
    convert_kernel<<<(N_EDGES + 255) / 256, 256>>>(eidx);
    scan1_kernel  <<<SCAN_BLOCKS, SCAN_CHUNK>>>();
    scan2_kernel  <<<1, 128>>>();
    scan3_kernel  <<<(N_NODES + 1 + 255) / 256, 256>>>(x);
    fill_kernel   <<<(N_EDGES + 255) / 256, 256>>>();

    // Layer 1: aggregate xs (8-d), then GEMM 8->64 (+b1, relu, *dinv for L2 agg)
    aggX_kernel<<<warpGrid, 256>>>();
    gemm_kernel<8, 64, 8, true, true><<<(N_NODES + 31) / 32, 256>>>(0, W1, b1, 1);
    // Layer 2: aggregate h1' (64-d) -> a2, then GEMM 64->128 (+b2, relu)
    agg64_kernel<false><<<warpGrid, 256>>>(1, 0, nullptr);
    gemm_kernel<64, 128, 8, true, false><<<(N_NODES + 15) / 16, 256>>>(0, W2, b2, 1);
    // Layer 3: GEMM 128->64 (*dinv), then aggregate (+b3, relu)
    gemm_kernel<128, 64, 4, false, true><<<(N_NODES + 15) / 16, 256>>>(1, W3, nullptr, 0);
    agg64_kernel<true><<<warpGrid, 256>>>(0, 1, b3);

    pool_kernel<<<(((N_NODES + 63) / 64) * 32 + 255) / 256, 256>>>(batch);
    mlp_kernel<<<1, 256>>>(Wl1, bl1, Wl2, bl2, out);
}

// round 8
// speedup vs baseline: 2.0551x; 1.2892x over previous
#include <cuda_runtime.h>

#define N_NODES  100000
#define N_EDGES  3200000
#define N_GRAPHS 256

static __device__ int   g_is64;
static __device__ int   g_ssrc[N_EDGES];      // src sorted by dst (CSR payload)
static __device__ int   g_cnt[N_NODES];
static __device__ int   g_rowptr[N_NODES + 1];
static __device__ int   g_cursor[N_NODES];
static __device__ float g_dinv[N_NODES];
static __device__ __align__(16) float g_xs[(size_t)N_NODES * 8];   // x * dinv
static __device__ __align__(16) float g_bufA[(size_t)N_NODES * 128];
static __device__ __align__(16) float g_bufB[(size_t)N_NODES * 128];
static __device__ float g_psum[N_GRAPHS * 64];
static __device__ int   g_pcnt[N_GRAPHS];
static __device__ int   g_bsum[128];
static __device__ int   g_boff[128];

static constexpr int SCAN_CHUNK  = 1024;
static constexpr int SCAN_BLOCKS = (N_NODES + SCAN_CHUNK - 1) / SCAN_CHUNK;

// ------------------------------------------------------------- f32x2 helpers

typedef unsigned long long ull;

__device__ __forceinline__ ull pack2(float x, float y) {
    ull r; asm("mov.b64 %0, {%1,%2};" : "=l"(r) : "f"(x), "f"(y)); return r;
}
__device__ __forceinline__ float2 unpack2(ull v) {
    float x, y; asm("mov.b64 {%0,%1}, %2;" : "=f"(x), "=f"(y) : "l"(v));
    return make_float2(x, y);
}
__device__ __forceinline__ ull fma2(ull a, ull b, ull c) {
    ull d; asm("fma.rn.f32x2 %0, %1, %2, %3;" : "=l"(d) : "l"(a), "l"(b), "l"(c));
    return d;
}

// ---------------------------------------------------------------- utilities

__global__ void zero_detect_kernel(const int* __restrict__ ei32) {
    int i = blockIdx.x * blockDim.x + threadIdx.x;
    if (i < N_NODES)      g_cnt[i]  = 0;
    if (i < N_GRAPHS*64)  g_psum[i] = 0.f;
    if (i < N_GRAPHS)     g_pcnt[i] = 0;
    if (i == 0) {
        // int64 tensors have the high int32 word zero for values < 2^31
        int allz = 1;
        for (int k = 1; k < 256; k += 2) allz &= (ei32[k] == 0);
        g_is64 = allz;
    }
}

// Histogram of dst degrees; reads only the dst row of edge_index.
__global__ void hist_kernel(const void* __restrict__ eidx) {
    int e = blockIdx.x * blockDim.x + threadIdx.x;
    if (e >= N_EDGES) return;
    int d;
    if (g_is64) d = (int)((const long long*)eidx)[(size_t)N_EDGES + e];
    else        d = ((const int*)eidx)[N_EDGES + e];
    atomicAdd(&g_cnt[d], 1);
}

// ---------------------------------------------------------------- prefix scan

__global__ void scan1_kernel() {
    __shared__ int s[SCAN_CHUNK];
    int tid = threadIdx.x;
    int i = blockIdx.x * SCAN_CHUNK + tid;
    int v = (i < N_NODES) ? g_cnt[i] : 0;
    s[tid] = v;
    __syncthreads();
    for (int off = 1; off < SCAN_CHUNK; off <<= 1) {
        int t = (tid >= off) ? s[tid - off] : 0;
        __syncthreads();
        s[tid] += t;
        __syncthreads();
    }
    if (i < N_NODES) g_rowptr[i] = s[tid] - v;   // exclusive, pre-offset
    if (tid == SCAN_CHUNK - 1) g_bsum[blockIdx.x] = s[tid];
}

__global__ void scan2_kernel() {
    __shared__ int s[128];
    int t = threadIdx.x;
    int v = (t < SCAN_BLOCKS) ? g_bsum[t] : 0;
    s[t] = v;
    __syncthreads();
    for (int off = 1; off < 128; off <<= 1) {
        int u = (t >= off) ? s[t - off] : 0;
        __syncthreads();
        s[t] += u;
        __syncthreads();
    }
    if (t < SCAN_BLOCKS) g_boff[t] = s[t] - v;
}

// Finalize rowptr/cursor; compute dinv; pre-scale x by dinv (xs = x * dinv).
__global__ void scan3_kernel(const float* __restrict__ x) {
    int i = blockIdx.x * blockDim.x + threadIdx.x;
    if (i > N_NODES) return;
    if (i == N_NODES) { g_rowptr[N_NODES] = N_EDGES; return; }
    int rp = g_rowptr[i] + g_boff[i / SCAN_CHUNK];
    g_rowptr[i] = rp;
    g_cursor[i] = rp;
    float deg = (float)g_cnt[i] + 1.0f;
    float dv = rsqrtf(deg);
    g_dinv[i] = dv;
    const float4* xp = (const float4*)(x + (size_t)i * 8);
    float4 u = xp[0], v4 = xp[1];
    float4* op = (float4*)(g_xs + (size_t)i * 8);
    op[0] = make_float4(u.x * dv, u.y * dv, u.z * dv, u.w * dv);
    op[1] = make_float4(v4.x * dv, v4.y * dv, v4.z * dv, v4.w * dv);
}

// Cursor-scatter into CSR; reads edge_index directly (no staging).
__global__ void fill_kernel(const void* __restrict__ eidx) {
    int e = blockIdx.x * blockDim.x + threadIdx.x;
    if (e >= N_EDGES) return;
    int s, d;
    if (g_is64) {
        const long long* p = (const long long*)eidx;
        s = (int)p[e];
        d = (int)p[(size_t)N_EDGES + e];
    } else {
        const int* p = (const int*)eidx;
        s = p[e];
        d = p[N_EDGES + e];
    }
    int slot = atomicAdd(&g_cursor[d], 1);
    g_ssrc[slot] = s;
}

// ------------------------------------------------- layer 1: fused agg + GEMM
//
// With h' = dinv*h pre-scaled, GCN aggregation is out_i = dinv_i*(h'_i + sum h'_j).
// One warp per node: gather-sum xs (8-d), butterfly-reduce (leaves the FULL sum
// in every lane), then each lane computes 2 columns of the 8->64 GEMM + bias +
// relu + dinv pre-scale for the next layer. Output: g_bufA, stride 64.
__global__ void aggX_gemm1_kernel(const float* __restrict__ W1,
                                  const float* __restrict__ b1) {
    __shared__ float sW[8 * 64];
    __shared__ float sB[64];
    int tid = threadIdx.x;
    for (int i = tid; i < 512; i += 256) sW[i] = W1[i];
    if (tid < 64) sB[tid] = b1[tid];
    __syncthreads();

    int w = (blockIdx.x * blockDim.x + tid) >> 5;
    if (w >= N_NODES) return;
    int lane = tid & 31;
    int beg = g_rowptr[w], end = g_rowptr[w + 1];
    float a0=0,a1=0,a2=0,a3=0,a4=0,a5=0,a6=0,a7=0;
    for (int e = beg + lane; e < end; e += 32) {
        int s = g_ssrc[e];
        const float4* xp = (const float4*)(g_xs + (size_t)s * 8);
        float4 u = xp[0], v = xp[1];
        a0 += u.x; a1 += u.y; a2 += u.z; a3 += u.w;
        a4 += v.x; a5 += v.y; a6 += v.z; a7 += v.w;
    }
    #pragma unroll
    for (int off = 16; off; off >>= 1) {
        a0 += __shfl_xor_sync(0xffffffffu, a0, off);
        a1 += __shfl_xor_sync(0xffffffffu, a1, off);
        a2 += __shfl_xor_sync(0xffffffffu, a2, off);
        a3 += __shfl_xor_sync(0xffffffffu, a3, off);
        a4 += __shfl_xor_sync(0xffffffffu, a4, off);
        a5 += __shfl_xor_sync(0xffffffffu, a5, off);
        a6 += __shfl_xor_sync(0xffffffffu, a6, off);
        a7 += __shfl_xor_sync(0xffffffffu, a7, off);
    }
    float dv = g_dinv[w];
    const float4* xp = (const float4*)(g_xs + (size_t)w * 8);
    float4 u = xp[0], v = xp[1];
    float s[8];
    s[0]=dv*(a0+u.x); s[1]=dv*(a1+u.y); s[2]=dv*(a2+u.z); s[3]=dv*(a3+u.w);
    s[4]=dv*(a4+v.x); s[5]=dv*(a5+v.y); s[6]=dv*(a6+v.z); s[7]=dv*(a7+v.w);
    int c = lane * 2;
    float o0 = sB[c], o1 = sB[c + 1];
    #pragma unroll
    for (int k = 0; k < 8; k++) {
        float2 wv = *(const float2*)&sW[k * 64 + c];
        o0 = fmaf(s[k], wv.x, o0);
        o1 = fmaf(s[k], wv.y, o1);
    }
    o0 = fmaxf(o0, 0.f) * dv;
    o1 = fmaxf(o1, 0.f) * dv;
    *(float2*)(g_bufA + (size_t)w * 64 + c) = make_float2(o0, o1);
}

// ---------------------------------------------------------------- aggregation

// F=64 aggregation. One warp per dst node, lane owns a float2 column pair.
// Pure gather+add inner loop (normalization pre-folded into the features).
template <bool BIAS_RELU>
__global__ void agg64_kernel(int inB, int outB, const float* __restrict__ bias) {
    int w = (blockIdx.x * blockDim.x + threadIdx.x) >> 5;
    if (w >= N_NODES) return;
    int lane = threadIdx.x & 31;
    int c = lane * 2;
    const float* __restrict__ in  = inB  ? g_bufB : g_bufA;
    float*       __restrict__ out = outB ? g_bufB : g_bufA;
    int e = g_rowptr[w], end = g_rowptr[w + 1];
    float ax0=0, ay0=0, ax1=0, ay1=0, ax2=0, ay2=0, ax3=0, ay3=0;
    for (; e + 4 <= end; e += 4) {
        int s0 = g_ssrc[e+0], s1 = g_ssrc[e+1], s2 = g_ssrc[e+2], s3 = g_ssrc[e+3];
        float2 v0 = *(const float2*)(in + (size_t)s0*64 + c);
        float2 v1 = *(const float2*)(in + (size_t)s1*64 + c);
        float2 v2 = *(const float2*)(in + (size_t)s2*64 + c);
        float2 v3 = *(const float2*)(in + (size_t)s3*64 + c);
        ax0 += v0.x; ay0 += v0.y;
        ax1 += v1.x; ay1 += v1.y;
        ax2 += v2.x; ay2 += v2.y;
        ax3 += v3.x; ay3 += v3.y;
    }
    for (; e < end; e++) {
        int s = g_ssrc[e];
        float2 v = *(const float2*)(in + (size_t)s*64 + c);
        ax0 += v.x; ay0 += v.y;
    }
    float dv = g_dinv[w];
    float2 sv = *(const float2*)(in + (size_t)w*64 + c);
    float ox = dv * ((ax0 + ax1) + (ax2 + ax3) + sv.x);
    float oy = dv * ((ay0 + ay1) + (ay2 + ay3) + sv.y);
    if (BIAS_RELU) {
        ox = fmaxf(ox + bias[c],     0.f);
        oy = fmaxf(oy + bias[c + 1], 0.f);
    }
    *(float2*)(out + (size_t)w*64 + c) = make_float2(ox, oy);
}

// ---------------------------------------------------------------- tiled GEMM
//
// Register-tiled node-parallel GEMM: each thread computes MPT nodes x CPT cols,
// amortizing the W smem stream MPT-fold (the simple version was LDS-bound at
// 4B/FMA) and using fma.rn.f32x2 for 2x fp32 FMA issue.
template <int IN, int OUT, int CPT, int MPT, bool ACT, bool SCALE>
__global__ void gemm_tiled_kernel(int inB, const float* __restrict__ W,
                                  const float* __restrict__ bias, int outB) {
    constexpr int TPN = OUT / CPT;            // col-groups
    constexpr int NL  = 256 / TPN;            // node-lanes per block
    constexpr int NPB = NL * MPT;             // nodes per block
    constexpr int HP  = IN + 1;               // padded sH row (bank spread)
    extern __shared__ float smem[];
    float* sW = smem;                         // IN*OUT
    float* sH = smem + IN * OUT;              // NPB*HP
    float* sB = sH + NPB * HP;                // OUT
    const float* __restrict__ in  = inB  ? g_bufB : g_bufA;
    float*       __restrict__ out = outB ? g_bufB : g_bufA;
    int tid = threadIdx.x;
    for (int i = tid; i < IN * OUT; i += 256) sW[i] = W[i];
    for (int i = tid; i < OUT; i += 256) sB[i] = bias ? bias[i] : 0.f;
    int base = blockIdx.x * NPB;
    for (int i = tid; i < NPB * IN; i += 256) {
        int nd = i / IN, k = i % IN;
        int node = base + nd;
        sH[nd * HP + k] = (node < N_NODES) ? in[(size_t)node * IN + k] : 0.f;
    }
    __syncthreads();

    int cg = tid % TPN;                       // column group
    int nl = tid / TPN;                       // node lane
    ull acc[MPT][CPT / 2];
    #pragma unroll
    for (int j = 0; j < MPT; j++)
        #pragma unroll
        for (int q = 0; q < CPT / 2; q++)
            acc[j][q] = pack2(sB[cg*CPT + 2*q], sB[cg*CPT + 2*q + 1]);

    #pragma unroll 4
    for (int k = 0; k < IN; k++) {
        const ull* wp = reinterpret_cast<const ull*>(sW + k * OUT + cg * CPT);
        ull wv[CPT / 2];
        #pragma unroll
        for (int q = 0; q < CPT / 2; q++) wv[q] = wp[q];
        #pragma unroll
        for (int j = 0; j < MPT; j++) {
            float a = sH[(nl * MPT + j) * HP + k];
            ull ap = pack2(a, a);
            #pragma unroll
            for (int q = 0; q < CPT / 2; q++)
                acc[j][q] = fma2(ap, wv[q], acc[j][q]);
        }
    }

    #pragma unroll
    for (int j = 0; j < MPT; j++) {
        int node = base + nl * MPT + j;
        if (node >= N_NODES) continue;
        float dv = SCALE ? g_dinv[node] : 1.0f;
        float* op = out + (size_t)node * OUT + cg * CPT;
        #pragma unroll
        for (int q = 0; q < CPT / 2; q++) {
            float2 v = unpack2(acc[j][q]);
            if (ACT) { v.x = fmaxf(v.x, 0.f); v.y = fmaxf(v.y, 0.f); }
            if (SCALE) { v.x *= dv; v.y *= dv; }
            *(float2*)(op + 2*q) = v;
        }
    }
}

// ---------------------------------------------------------------- pooling + MLP

__global__ void pool_kernel(const void* __restrict__ batch) {
    int w = (blockIdx.x * blockDim.x + threadIdx.x) >> 5;
    int lane = threadIdx.x & 31;
    const int NPW = 64;
    int start = w * NPW;
    if (start >= N_NODES) return;
    int end = min(start + NPW, N_NODES);
    int is64 = g_is64;
    int c = lane * 2;
    float ax = 0.f, ay = 0.f;
    int curg = -1, cnt = 0;
    for (int i = start; i < end; i++) {
        int g = is64 ? (int)((const long long*)batch)[i] : ((const int*)batch)[i];
        if (g != curg) {
            if (curg >= 0) {
                atomicAdd(&g_psum[curg * 64 + c],     ax);
                atomicAdd(&g_psum[curg * 64 + c + 1], ay);
                if (lane == 0) atomicAdd(&g_pcnt[curg], cnt);
            }
            curg = g; ax = 0.f; ay = 0.f; cnt = 0;
        }
        float2 v = *(const float2*)(g_bufA + (size_t)i * 64 + c);
        ax += v.x; ay += v.y; cnt++;
    }
    if (curg >= 0) {
        atomicAdd(&g_psum[curg * 64 + c],     ax);
        atomicAdd(&g_psum[curg * 64 + c + 1], ay);
        if (lane == 0) atomicAdd(&g_pcnt[curg], cnt);
    }
}

__global__ void mlp_kernel(const float* __restrict__ Wl1, const float* __restrict__ bl1,
                           const float* __restrict__ Wl2, const float* __restrict__ bl2,
                           float* __restrict__ out) {
    __shared__ float sW1[64 * 32];
    __shared__ float sb1[32];
    __shared__ float sW2[32];
    __shared__ float sb2;
    int tid = threadIdx.x;
    for (int i = tid; i < 64 * 32; i += 256) sW1[i] = Wl1[i];
    if (tid < 32) { sb1[tid] = bl1[tid]; sW2[tid] = Wl2[tid]; }
    if (tid == 0) sb2 = bl2[0];
    __syncthreads();
    float inv = 1.0f / fmaxf((float)g_pcnt[tid], 1.0f);
    float hid[32];
    #pragma unroll
    for (int cc = 0; cc < 32; cc++) hid[cc] = sb1[cc];
    for (int k = 0; k < 64; k++) {
        float a = g_psum[tid * 64 + k] * inv;
        #pragma unroll
        for (int cc = 0; cc < 32; cc++) hid[cc] = fmaf(a, sW1[k * 32 + cc], hid[cc]);
    }
    float o = sb2;
    #pragma unroll
    for (int cc = 0; cc < 32; cc++) o = fmaf(fmaxf(hid[cc], 0.f), sW2[cc], o);
    out[tid] = o;
}

// ---------------------------------------------------------------- launch

extern "C" void kernel_launch(void* const* d_in, const int* in_sizes, int n_in,
                              void* d_out, int out_size) {
    const float* x    = (const float*)d_in[0];
    const void*  eidx = d_in[1];
    const void*  batch= d_in[2];
    const float* W1   = (const float*)d_in[3];
    const float* b1   = (const float*)d_in[4];
    const float* W2   = (const float*)d_in[5];
    const float* b2   = (const float*)d_in[6];
    const float* W3   = (const float*)d_in[7];
    const float* b3   = (const float*)d_in[8];
    const float* Wl1  = (const float*)d_in[9];
    const float* bl1  = (const float*)d_in[10];
    const float* Wl2  = (const float*)d_in[11];
    const float* bl2  = (const float*)d_in[12];
    float* out = (float*)d_out;

    // gemm2: 64->128, CPT=8, MPT=4 -> NPB=64. smem = 64*128 + 64*65 + 128 floats
    constexpr int SM2 = (64*128 + 64*65 + 128) * 4;
    // gemm3: 128->64, CPT=8, MPT=2 -> NPB=64. smem = 128*64 + 64*129 + 64 floats
    constexpr int SM3 = (128*64 + 64*129 + 64) * 4;
    cudaFuncSetAttribute(gemm_tiled_kernel<64,128,8,4,true,false>,
                         cudaFuncAttributeMaxDynamicSharedMemorySize, SM2);
    cudaFuncSetAttribute(gemm_tiled_kernel<128,64,8,2,false,true>,
                         cudaFuncAttributeMaxDynamicSharedMemorySize, SM3);

    const int warpGrid = (N_NODES * 32 + 255) / 256;
    const int tileGrid = (N_NODES + 63) / 64;

    zero_detect_kernel<<<(N_NODES + 255) / 256, 256>>>((const int*)eidx);
    hist_kernel  <<<(N_EDGES + 255) / 256, 256>>>(eidx);
    scan1_kernel <<<SCAN_BLOCKS, SCAN_CHUNK>>>();
    scan2_kernel <<<1, 128>>>();
    scan3_kernel <<<(N_NODES + 1 + 255) / 256, 256>>>(x);
    fill_kernel  <<<(N_EDGES + 255) / 256, 256>>>(eidx);

    // Layer 1 (fused): agg xs (8-d) + GEMM 8->64 + b1 + relu + dinv -> bufA
    aggX_gemm1_kernel<<<warpGrid, 256>>>(W1, b1);
    // Layer 2: aggregate (bufA->bufB), GEMM 64->128 + b2 + relu (bufB->bufA)
    agg64_kernel<false><<<warpGrid, 256>>>(0, 1, nullptr);
    gemm_tiled_kernel<64,128,8,4,true,false><<<tileGrid, 256, SM2>>>(1, W2, b2, 0);
    // Layer 3: GEMM 128->64 * dinv (bufA->bufB), aggregate + b3 + relu (bufB->bufA)
    gemm_tiled_kernel<128,64,8,2,false,true><<<tileGrid, 256, SM3>>>(0, W3, nullptr, 1);
    agg64_kernel<true><<<warpGrid, 256>>>(1, 0, b3);

    pool_kernel<<<(((N_NODES + 63) / 64) * 32 + 255) / 256, 256>>>(batch);
    mlp_kernel<<<1, 256>>>(Wl1, bl1, Wl2, bl2, out);
}

// round 13
// speedup vs baseline: 2.0923x; 1.0181x over previous
#include <cuda_runtime.h>
#include <cuda_fp16.h>

#define N_NODES  100000
#define N_EDGES  3200000
#define N_GRAPHS 256

static __device__ int   g_is64;
static __device__ int   g_ssrc[N_EDGES];      // src sorted by dst (CSR payload)
static __device__ int   g_cnt[N_NODES];
static __device__ int   g_rowptr[N_NODES + 1];
static __device__ int   g_cursor[N_NODES];
static __device__ float g_dinv[N_NODES];
static __device__ __align__(16) float   g_xs[(size_t)N_NODES * 8];    // x * dinv
static __device__ __align__(16) float   g_bufA[(size_t)N_NODES * 128];
static __device__ __align__(16) float   g_bufB[(size_t)N_NODES * 64];
static __device__ __align__(16) __half2 g_hbuf[(size_t)N_NODES * 32]; // agg-only features
static __device__ float g_psum[N_GRAPHS * 64];
static __device__ int   g_pcnt[N_GRAPHS];
static __device__ int   g_bsum[128];
static __device__ int   g_boff[128];

static constexpr int SCAN_CHUNK  = 1024;
static constexpr int SCAN_BLOCKS = (N_NODES + SCAN_CHUNK - 1) / SCAN_CHUNK;

// ------------------------------------------------------------- f32x2 helpers

typedef unsigned long long ull;

__device__ __forceinline__ ull pack2(float x, float y) {
    ull r; asm("mov.b64 %0, {%1,%2};" : "=l"(r) : "f"(x), "f"(y)); return r;
}
__device__ __forceinline__ float2 unpack2(ull v) {
    float x, y; asm("mov.b64 {%0,%1}, %2;" : "=f"(x), "=f"(y) : "l"(v));
    return make_float2(x, y);
}
__device__ __forceinline__ ull fma2(ull a, ull b, ull c) {
    ull d; asm("fma.rn.f32x2 %0, %1, %2, %3;" : "=l"(d) : "l"(a), "l"(b), "l"(c));
    return d;
}

// ---------------------------------------------------------------- utilities

__global__ void zero_detect_kernel(const int* __restrict__ ei32) {
    int i = blockIdx.x * blockDim.x + threadIdx.x;
    if (i < N_NODES)      g_cnt[i]  = 0;
    if (i < N_GRAPHS*64)  g_psum[i] = 0.f;
    if (i < N_GRAPHS)     g_pcnt[i] = 0;
    if (i == 0) {
        // int64 tensors have the high int32 word zero for values < 2^31
        int allz = 1;
        for (int k = 1; k < 256; k += 2) allz &= (ei32[k] == 0);
        g_is64 = allz;
    }
}

// Histogram of dst degrees; reads only the dst row of edge_index.
__global__ void hist_kernel(const void* __restrict__ eidx) {
    int e = blockIdx.x * blockDim.x + threadIdx.x;
    if (e >= N_EDGES) return;
    int d;
    if (g_is64) d = (int)((const long long*)eidx)[(size_t)N_EDGES + e];
    else        d = ((const int*)eidx)[N_EDGES + e];
    atomicAdd(&g_cnt[d], 1);
}

// ---------------------------------------------------------------- prefix scan

__global__ void scan1_kernel() {
    __shared__ int s[SCAN_CHUNK];
    int tid = threadIdx.x;
    int i = blockIdx.x * SCAN_CHUNK + tid;
    int v = (i < N_NODES) ? g_cnt[i] : 0;
    s[tid] = v;
    __syncthreads();
    for (int off = 1; off < SCAN_CHUNK; off <<= 1) {
        int t = (tid >= off) ? s[tid - off] : 0;
        __syncthreads();
        s[tid] += t;
        __syncthreads();
    }
    if (i < N_NODES) g_rowptr[i] = s[tid] - v;   // exclusive, pre-offset
    if (tid == SCAN_CHUNK - 1) g_bsum[blockIdx.x] = s[tid];
}

__global__ void scan2_kernel() {
    __shared__ int s[128];
    int t = threadIdx.x;
    int v = (t < SCAN_BLOCKS) ? g_bsum[t] : 0;
    s[t] = v;
    __syncthreads();
    for (int off = 1; off < 128; off <<= 1) {
        int u = (t >= off) ? s[t - off] : 0;
        __syncthreads();
        s[t] += u;
        __syncthreads();
    }
    if (t < SCAN_BLOCKS) g_boff[t] = s[t] - v;
}

// Finalize rowptr/cursor; compute dinv; pre-scale x by dinv (xs = x * dinv).
__global__ void scan3_kernel(const float* __restrict__ x) {
    int i = blockIdx.x * blockDim.x + threadIdx.x;
    if (i > N_NODES) return;
    if (i == N_NODES) { g_rowptr[N_NODES] = N_EDGES; return; }
    int rp = g_rowptr[i] + g_boff[i / SCAN_CHUNK];
    g_rowptr[i] = rp;
    g_cursor[i] = rp;
    float deg = (float)g_cnt[i] + 1.0f;
    float dv = rsqrtf(deg);
    g_dinv[i] = dv;
    const float4* xp = (const float4*)(x + (size_t)i * 8);
    float4 u = xp[0], v4 = xp[1];
    float4* op = (float4*)(g_xs + (size_t)i * 8);
    op[0] = make_float4(u.x * dv, u.y * dv, u.z * dv, u.w * dv);
    op[1] = make_float4(v4.x * dv, v4.y * dv, v4.z * dv, v4.w * dv);
}

// Cursor-scatter into CSR; reads edge_index directly (no staging).
__global__ void fill_kernel(const void* __restrict__ eidx) {
    int e = blockIdx.x * blockDim.x + threadIdx.x;
    if (e >= N_EDGES) return;
    int s, d;
    if (g_is64) {
        const long long* p = (const long long*)eidx;
        s = (int)p[e];
        d = (int)p[(size_t)N_EDGES + e];
    } else {
        const int* p = (const int*)eidx;
        s = p[e];
        d = p[N_EDGES + e];
    }
    int slot = atomicAdd(&g_cursor[d], 1);
    g_ssrc[slot] = s;
}

// ------------------------------------------------- layer 1: fused agg + GEMM
//
// With h' = dinv*h pre-scaled, GCN aggregation is out_i = dinv_i*(h'_i + sum h'_j).
// One warp per node: gather-sum xs (8-d), butterfly-reduce (full sum in every
// lane), each lane computes 2 cols of the 8->64 GEMM + bias + relu + dinv
// pre-scale, stored as half2 (consumed only by the layer-2 aggregation).
__global__ void aggX_gemm1_kernel(const float* __restrict__ W1,
                                  const float* __restrict__ b1) {
    __shared__ float sW[8 * 64];
    __shared__ float sB[64];
    int tid = threadIdx.x;
    for (int i = tid; i < 512; i += 256) sW[i] = W1[i];
    if (tid < 64) sB[tid] = b1[tid];
    __syncthreads();

    int w = (blockIdx.x * blockDim.x + tid) >> 5;
    if (w >= N_NODES) return;
    int lane = tid & 31;
    int beg = g_rowptr[w], end = g_rowptr[w + 1];
    float a0=0,a1=0,a2=0,a3=0,a4=0,a5=0,a6=0,a7=0;
    for (int e = beg + lane; e < end; e += 32) {
        int s = g_ssrc[e];
        const float4* xp = (const float4*)(g_xs + (size_t)s * 8);
        float4 u = xp[0], v = xp[1];
        a0 += u.x; a1 += u.y; a2 += u.z; a3 += u.w;
        a4 += v.x; a5 += v.y; a6 += v.z; a7 += v.w;
    }
    #pragma unroll
    for (int off = 16; off; off >>= 1) {
        a0 += __shfl_xor_sync(0xffffffffu, a0, off);
        a1 += __shfl_xor_sync(0xffffffffu, a1, off);
        a2 += __shfl_xor_sync(0xffffffffu, a2, off);
        a3 += __shfl_xor_sync(0xffffffffu, a3, off);
        a4 += __shfl_xor_sync(0xffffffffu, a4, off);
        a5 += __shfl_xor_sync(0xffffffffu, a5, off);
        a6 += __shfl_xor_sync(0xffffffffu, a6, off);
        a7 += __shfl_xor_sync(0xffffffffu, a7, off);
    }
    float dv = g_dinv[w];
    const float4* xp = (const float4*)(g_xs + (size_t)w * 8);
    float4 u = xp[0], v = xp[1];
    float s[8];
    s[0]=dv*(a0+u.x); s[1]=dv*(a1+u.y); s[2]=dv*(a2+u.z); s[3]=dv*(a3+u.w);
    s[4]=dv*(a4+v.x); s[5]=dv*(a5+v.y); s[6]=dv*(a6+v.z); s[7]=dv*(a7+v.w);
    int c = lane * 2;
    float o0 = sB[c], o1 = sB[c + 1];
    #pragma unroll
    for (int k = 0; k < 8; k++) {
        float2 wv = *(const float2*)&sW[k * 64 + c];
        o0 = fmaf(s[k], wv.x, o0);
        o1 = fmaf(s[k], wv.y, o1);
    }
    o0 = fmaxf(o0, 0.f) * dv;
    o1 = fmaxf(o1, 0.f) * dv;
    g_hbuf[(size_t)w * 32 + lane] = __floats2half2_rn(o0, o1);
}

// ---------------------------------------------------------------- aggregation

// F=64 aggregation from the half2 feature buffer. One warp per dst node, lane
// owns one half2 column pair; fp32 accumulation; 8-way edge unroll for MLP.
// outSel: 0 -> g_bufA, 1 -> g_bufB (resolved IN-KERNEL; device symbols must
// never be passed as host-side kernel arguments).
template <bool BIAS_RELU>
__global__ void agg64h_kernel(int outSel, const float* __restrict__ bias) {
    int w = (blockIdx.x * blockDim.x + threadIdx.x) >> 5;
    if (w >= N_NODES) return;
    int lane = threadIdx.x & 31;
    float* __restrict__ out = outSel ? g_bufB : g_bufA;
    const __half2* __restrict__ in = g_hbuf;
    int e = g_rowptr[w], end = g_rowptr[w + 1];
    float ax0=0, ay0=0, ax1=0, ay1=0, ax2=0, ay2=0, ax3=0, ay3=0;
    for (; e + 8 <= end; e += 8) {
        int s0 = g_ssrc[e+0], s1 = g_ssrc[e+1], s2 = g_ssrc[e+2], s3 = g_ssrc[e+3];
        int s4 = g_ssrc[e+4], s5 = g_ssrc[e+5], s6 = g_ssrc[e+6], s7 = g_ssrc[e+7];
        __half2 h0 = in[(size_t)s0*32 + lane];
        __half2 h1 = in[(size_t)s1*32 + lane];
        __half2 h2 = in[(size_t)s2*32 + lane];
        __half2 h3 = in[(size_t)s3*32 + lane];
        __half2 h4 = in[(size_t)s4*32 + lane];
        __half2 h5 = in[(size_t)s5*32 + lane];
        __half2 h6 = in[(size_t)s6*32 + lane];
        __half2 h7 = in[(size_t)s7*32 + lane];
        float2 f0 = __half22float2(h0), f1 = __half22float2(h1);
        float2 f2 = __half22float2(h2), f3 = __half22float2(h3);
        float2 f4 = __half22float2(h4), f5 = __half22float2(h5);
        float2 f6 = __half22float2(h6), f7 = __half22float2(h7);
        ax0 += f0.x; ay0 += f0.y;  ax1 += f1.x; ay1 += f1.y;
        ax2 += f2.x; ay2 += f2.y;  ax3 += f3.x; ay3 += f3.y;
        ax0 += f4.x; ay0 += f4.y;  ax1 += f5.x; ay1 += f5.y;
        ax2 += f6.x; ay2 += f6.y;  ax3 += f7.x; ay3 += f7.y;
    }
    for (; e < end; e++) {
        int s = g_ssrc[e];
        float2 f = __half22float2(in[(size_t)s*32 + lane]);
        ax0 += f.x; ay0 += f.y;
    }
    float dv = g_dinv[w];
    float2 sv = __half22float2(in[(size_t)w*32 + lane]);
    float ox = dv * ((ax0 + ax1) + (ax2 + ax3) + sv.x);
    float oy = dv * ((ay0 + ay1) + (ay2 + ay3) + sv.y);
    int c = lane * 2;
    if (BIAS_RELU) {
        ox = fmaxf(ox + bias[c],     0.f);
        oy = fmaxf(oy + bias[c + 1], 0.f);
    }
    *(float2*)(out + (size_t)w*64 + c) = make_float2(ox, oy);
}

// ---------------------------------------------------------------- tiled GEMM
//
// Register-tiled node-parallel GEMM: each thread computes MPT nodes x CPT cols,
// amortizing the W smem stream MPT-fold, with fma.rn.f32x2 for 2x fp32 issue.
// inSel/outSel: 0 -> g_bufA, 1 -> g_bufB (in-kernel). OUTH: write half2 to g_hbuf.
template <int IN, int OUT, int CPT, int MPT, bool ACT, bool SCALE, bool OUTH>
__global__ void gemm_tiled_kernel(int inSel, const float* __restrict__ W,
                                  const float* __restrict__ bias, int outSel) {
    constexpr int TPN = OUT / CPT;            // col-groups
    constexpr int NL  = 256 / TPN;            // node-lanes per block
    constexpr int NPB = NL * MPT;             // nodes per block
    constexpr int HP  = IN + 1;               // padded sH row (bank spread)
    extern __shared__ float smem[];
    float* sW = smem;                         // IN*OUT
    float* sH = smem + IN * OUT;              // NPB*HP
    float* sB = sH + NPB * HP;                // OUT
    const float* __restrict__ in_p  = inSel  ? g_bufB : g_bufA;
    float*       __restrict__ out_p = outSel ? g_bufB : g_bufA;
    int tid = threadIdx.x;
    for (int i = tid; i < IN * OUT; i += 256) sW[i] = W[i];
    for (int i = tid; i < OUT; i += 256) sB[i] = bias ? bias[i] : 0.f;
    int base = blockIdx.x * NPB;
    for (int i = tid; i < NPB * IN; i += 256) {
        int nd = i / IN, k = i % IN;
        int node = base + nd;
        sH[nd * HP + k] = (node < N_NODES) ? in_p[(size_t)node * IN + k] : 0.f;
    }
    __syncthreads();

    int cg = tid % TPN;                       // column group
    int nl = tid / TPN;                       // node lane
    ull acc[MPT][CPT / 2];
    #pragma unroll
    for (int j = 0; j < MPT; j++)
        #pragma unroll
        for (int q = 0; q < CPT / 2; q++)
            acc[j][q] = pack2(sB[cg*CPT + 2*q], sB[cg*CPT + 2*q + 1]);

    #pragma unroll 4
    for (int k = 0; k < IN; k++) {
        const ull* wp = reinterpret_cast<const ull*>(sW + k * OUT + cg * CPT);
        ull wv[CPT / 2];
        #pragma unroll
        for (int q = 0; q < CPT / 2; q++) wv[q] = wp[q];
        #pragma unroll
        for (int j = 0; j < MPT; j++) {
            float a = sH[(nl * MPT + j) * HP + k];
            ull ap = pack2(a, a);
            #pragma unroll
            for (int q = 0; q < CPT / 2; q++)
                acc[j][q] = fma2(ap, wv[q], acc[j][q]);
        }
    }

    #pragma unroll
    for (int j = 0; j < MPT; j++) {
        int node = base + nl * MPT + j;
        if (node >= N_NODES) continue;
        float dv = SCALE ? g_dinv[node] : 1.0f;
        #pragma unroll
        for (int q = 0; q < CPT / 2; q++) {
            float2 v = unpack2(acc[j][q]);
            if (ACT) { v.x = fmaxf(v.x, 0.f); v.y = fmaxf(v.y, 0.f); }
            if (SCALE) { v.x *= dv; v.y *= dv; }
            if (OUTH) {
                g_hbuf[(size_t)node * 32 + (cg * CPT) / 2 + q] =
                    __floats2half2_rn(v.x, v.y);
            } else {
                *(float2*)(out_p + (size_t)node * OUT + cg * CPT + 2*q) = v;
            }
        }
    }
}

// ---------------------------------------------------------------- pooling + MLP

__global__ void pool_kernel(const void* __restrict__ batch) {
    int w = (blockIdx.x * blockDim.x + threadIdx.x) >> 5;
    int lane = threadIdx.x & 31;
    const int NPW = 64;
    int start = w * NPW;
    if (start >= N_NODES) return;
    int end = min(start + NPW, N_NODES);
    int is64 = g_is64;
    int c = lane * 2;
    float ax = 0.f, ay = 0.f;
    int curg = -1, cnt = 0;
    for (int i = start; i < end; i++) {
        int g = is64 ? (int)((const long long*)batch)[i] : ((const int*)batch)[i];
        if (g != curg) {
            if (curg >= 0) {
                atomicAdd(&g_psum[curg * 64 + c],     ax);
                atomicAdd(&g_psum[curg * 64 + c + 1], ay);
                if (lane == 0) atomicAdd(&g_pcnt[curg], cnt);
            }
            curg = g; ax = 0.f; ay = 0.f; cnt = 0;
        }
        float2 v = *(const float2*)(g_bufA + (size_t)i * 64 + c);
        ax += v.x; ay += v.y; cnt++;
    }
    if (curg >= 0) {
        atomicAdd(&g_psum[curg * 64 + c],     ax);
        atomicAdd(&g_psum[curg * 64 + c + 1], ay);
        if (lane == 0) atomicAdd(&g_pcnt[curg], cnt);
    }
}

__global__ void mlp_kernel(const float* __restrict__ Wl1, const float* __restrict__ bl1,
                           const float* __restrict__ Wl2, const float* __restrict__ bl2,
                           float* __restrict__ out) {
    __shared__ float sW1[64 * 32];
    __shared__ float sb1[32];
    __shared__ float sW2[32];
    __shared__ float sb2;
    int tid = threadIdx.x;
    for (int i = tid; i < 64 * 32; i += 256) sW1[i] = Wl1[i];
    if (tid < 32) { sb1[tid] = bl1[tid]; sW2[tid] = Wl2[tid]; }
    if (tid == 0) sb2 = bl2[0];
    __syncthreads();
    float inv = 1.0f / fmaxf((float)g_pcnt[tid], 1.0f);
    float hid[32];
    #pragma unroll
    for (int cc = 0; cc < 32; cc++) hid[cc] = sb1[cc];
    for (int k = 0; k < 64; k++) {
        float a = g_psum[tid * 64 + k] * inv;
        #pragma unroll
        for (int cc = 0; cc < 32; cc++) hid[cc] = fmaf(a, sW1[k * 32 + cc], hid[cc]);
    }
    float o = sb2;
    #pragma unroll
    for (int cc = 0; cc < 32; cc++) o = fmaf(fmaxf(hid[cc], 0.f), sW2[cc], o);
    out[tid] = o;
}

// ---------------------------------------------------------------- launch

extern "C" void kernel_launch(void* const* d_in, const int* in_sizes, int n_in,
                              void* d_out, int out_size) {
    const float* x    = (const float*)d_in[0];
    const void*  eidx = d_in[1];
    const void*  batch= d_in[2];
    const float* W1   = (const float*)d_in[3];
    const float* b1   = (const float*)d_in[4];
    const float* W2   = (const float*)d_in[5];
    const float* b2   = (const float*)d_in[6];
    const float* W3   = (const float*)d_in[7];
    const float* b3   = (const float*)d_in[8];
    const float* Wl1  = (const float*)d_in[9];
    const float* bl1  = (const float*)d_in[10];
    const float* Wl2  = (const float*)d_in[11];
    const float* bl2  = (const float*)d_in[12];
    float* out = (float*)d_out;

    // gemm2: 64->128, CPT=8, MPT=4 -> NPB=64. smem = 64*128 + 64*65 + 128 floats
    constexpr int SM2 = (64*128 + 64*65 + 128) * 4;
    // gemm3: 128->64, CPT=8, MPT=2 -> NPB=64. smem = 128*64 + 64*129 + 64 floats
    constexpr int SM3 = (128*64 + 64*129 + 64) * 4;
    cudaFuncSetAttribute(gemm_tiled_kernel<64,128,8,4,true,false,false>,
                         cudaFuncAttributeMaxDynamicSharedMemorySize, SM2);
    cudaFuncSetAttribute(gemm_tiled_kernel<128,64,8,2,false,true,true>,
                         cudaFuncAttributeMaxDynamicSharedMemorySize, SM3);

    const int warpGrid = (N_NODES * 32 + 255) / 256;
    const int tileGrid = (N_NODES + 63) / 64;

    zero_detect_kernel<<<(N_NODES + 255) / 256, 256>>>((const int*)eidx);
    hist_kernel  <<<(N_EDGES + 255) / 256, 256>>>(eidx);
    scan1_kernel <<<SCAN_BLOCKS, SCAN_CHUNK>>>();
    scan2_kernel <<<1, 128>>>();
    scan3_kernel <<<(N_NODES + 1 + 255) / 256, 256>>>(x);
    fill_kernel  <<<(N_EDGES + 255) / 256, 256>>>(eidx);

    // Layer 1 (fused): agg xs (8-d) + GEMM 8->64 + b1 + relu + dinv -> hbuf (fp16)
    aggX_gemm1_kernel<<<warpGrid, 256>>>(W1, b1);
    // Layer 2: aggregate (hbuf -> bufB fp32), GEMM 64->128 + b2 + relu (bufB -> bufA)
    agg64h_kernel<false><<<warpGrid, 256>>>(1, nullptr);
    gemm_tiled_kernel<64,128,8,4,true,false,false><<<tileGrid, 256, SM2>>>(1, W2, b2, 0);
    // Layer 3: GEMM 128->64 * dinv (bufA -> hbuf fp16), aggregate + b3 + relu (-> bufA)
    gemm_tiled_kernel<128,64,8,2,false,true,true><<<tileGrid, 256, SM3>>>(0, W3, nullptr, 0);
    agg64h_kernel<true><<<warpGrid, 256>>>(0, b3);

    pool_kernel<<<(((N_NODES + 63) / 64) * 32 + 255) / 256, 256>>>(batch);
    mlp_kernel<<<1, 256>>>(Wl1, bl1, Wl2, bl2, out);
}